// round 13
// baseline (speedup 1.0000x reference)
#include <cuda_runtime.h>
#include <cuda_bf16.h>
#include <cstdint>

// Problem constants
#define SS   512
#define BB   256
#define DIN  202
#define HH   100
#define TT   19
#define MM   (SS*BB)   // 131072

// ---------------- scratch (device globals; no allocations allowed) ----------
__device__ uint32_t g_xp_bf[2ll * SS * BB * 50];   // bf16x2-packed xp
__device__ uint32_t g_h_pk[2ll * SS * BB * 50];    // bf16x2-packed hidden
__device__ float g_probs[(long long)SS * BB * TT]; // softmax emissions
__device__ float g_res[SS];                        // per-sequence CRF llh
__device__ __align__(16) uint32_t g_wih_img[224 * 108];  // bf16 W_ih image (K1 B)
__device__ __align__(16) uint32_t g_wtag_img[24 * 108];  // bf16 W_tag image (K3 B)

// ---------------- helpers ----------
typedef unsigned long long u64;

__device__ __forceinline__ uint32_t smem_u32(const void* p) {
    uint32_t a;
    asm("{ .reg .u64 t; cvta.to.shared.u64 t, %1; cvt.u32.u64 %0, t; }"
        : "=r"(a) : "l"(p));
    return a;
}
__device__ __forceinline__ uint32_t bf16x2(float lo, float hi) {
    uint32_t l = (uint32_t)__bfloat16_as_ushort(__float2bfloat16_rn(lo));
    uint32_t h = (uint32_t)__bfloat16_as_ushort(__float2bfloat16_rn(hi));
    return l | (h << 16);
}
__device__ __forceinline__ uint32_t bfpack2(float lo, float hi) {
    uint32_t r;
    asm("cvt.rn.bf16x2.f32 %0, %1, %2;" : "=r"(r) : "f"(hi), "f"(lo));
    return r;
}
__device__ __forceinline__ float bflo(uint32_t u) {
    return __uint_as_float(u << 16);
}
__device__ __forceinline__ float bfhi(uint32_t u) {
    return __uint_as_float(u & 0xffff0000u);
}

__device__ __forceinline__ void ldsm_x4(uint32_t a[4], uint32_t addr) {
    asm volatile("ldmatrix.sync.aligned.m8n8.x4.shared.b16 {%0,%1,%2,%3}, [%4];"
                 : "=r"(a[0]), "=r"(a[1]), "=r"(a[2]), "=r"(a[3]) : "r"(addr));
}
__device__ __forceinline__ void ldsm_x2(uint32_t a[2], uint32_t addr) {
    asm volatile("ldmatrix.sync.aligned.m8n8.x2.shared.b16 {%0,%1}, [%2];"
                 : "=r"(a[0]), "=r"(a[1]) : "r"(addr));
}
__device__ __forceinline__ void mma_bf16(float c[4], const uint32_t a[4],
                                         uint32_t b0, uint32_t b1) {
    asm volatile("mma.sync.aligned.m16n8k16.row.col.f32.bf16.bf16.f32 "
                 "{%0,%1,%2,%3}, {%4,%5,%6,%7}, {%8,%9}, {%0,%1,%2,%3};"
                 : "+f"(c[0]), "+f"(c[1]), "+f"(c[2]), "+f"(c[3])
                 : "r"(a[0]), "r"(a[1]), "r"(a[2]), "r"(a[3]),
                   "r"(b0), "r"(b1));
}
__device__ __forceinline__ void cp_async16(uint32_t dst, const void* src) {
    asm volatile("cp.async.cg.shared.global [%0], [%1], 16;"
                 :: "r"(dst), "l"(src) : "memory");
}
__device__ __forceinline__ void cp_async8(uint32_t dst, const void* src) {
    asm volatile("cp.async.ca.shared.global [%0], [%1], 8;"
                 :: "r"(dst), "l"(src) : "memory");
}

// ---------------------------------------------------------------------------
// K0 (prep): convert W_ih (both dirs) + W_tag to bf16 SMEM-image layouts.
// ---------------------------------------------------------------------------
__global__ void prep_kernel(const float* __restrict__ Wf,
                            const float* __restrict__ Wb,
                            const float* __restrict__ Wtag)
{
    int i = blockIdx.x * 256 + threadIdx.x;
    if (i < 224 * 108) {
        int j = i / 108, kp = i - j * 108, k = 2 * kp;
        int d = j >= 112, jj = j - d * 112;
        const float* W = d ? Wb : Wf;
        float w0 = 0.f, w1 = 0.f;
        if (jj < HH) {
            if (k < DIN)     w0 = W[jj * DIN + k];
            if (k + 1 < DIN) w1 = W[jj * DIN + k + 1];
        }
        g_wih_img[i] = bf16x2(w0, w1);
    } else if (i < 224 * 108 + 24 * 108) {
        int i2 = i - 224 * 108;
        int t = i2 / 108, kp = i2 - t * 108, k = 2 * kp;
        float w0 = 0.f, w1 = 0.f;
        if (t < TT) {
            if (k < 200)     w0 = Wtag[t * 200 + k];
            if (k + 1 < 200) w1 = Wtag[t * 200 + k + 1];
        }
        g_wtag_img[i2] = bf16x2(w0, w1);
    }
}

// ---------------------------------------------------------------------------
// K1 (mma.sync bf16, BOTH dirs fused) — unchanged (passing).
// ---------------------------------------------------------------------------
#define K1_STRIDE 216
#define K1_A_BYTES (128 * K1_STRIDE * 2)
#define K1_B_BYTES (224 * K1_STRIDE * 2)
#define K1_BIAS_OFF (K1_A_BYTES + K1_B_BYTES)
#define K1_SMEM (K1_BIAS_OFF + 208 * 4)

__global__ void proj_mma_kernel(const float* __restrict__ x,
                                const float* __restrict__ bihf,
                                const float* __restrict__ bhhf,
                                const float* __restrict__ bihb,
                                const float* __restrict__ bhhb)
{
    extern __shared__ __align__(16) char smem[];
    const uint32_t sbase = smem_u32(smem);
    float* bias_sh = (float*)(smem + K1_BIAS_OFF);

    const int tid = threadIdx.x;
    const int wid = tid >> 5;
    const int lane = tid & 31;
    const int r0  = blockIdx.x * 128;

    {
        const uint32_t sB = sbase + K1_A_BYTES;
        const char* src = (const char*)g_wih_img;
        for (int idx = tid; idx < 6048; idx += 256)
            cp_async16(sB + idx * 16, src + idx * 16);
    }

    if (tid < 208) {
        int d = tid >= 104, jj = tid - d * 104;
        const float* bi = d ? bihb : bihf;
        const float* bh = d ? bhhb : bhhf;
        bias_sh[tid] = (jj < HH) ? (bi[jj] + bh[jj]) : 0.f;
    }

    for (int idx = tid; idx < 128 * 104; idx += 256) {
        int r = idx / 104, kp = idx - r * 104, k = kp * 2;
        float2 xv = make_float2(0.f, 0.f);
        if (k < DIN) xv = *(const float2*)&x[(size_t)(r0 + r) * DIN + k];
        *(uint32_t*)(smem + r * 432 + kp * 4) = bf16x2(xv.x, xv.y);
    }
    asm volatile("cp.async.commit_group;" ::: "memory");
    asm volatile("cp.async.wait_group 0;" ::: "memory");
    __syncthreads();

    const int m0 = wid * 16;
    float accA[13][4], accB[13][4];
#pragma unroll
    for (int nt = 0; nt < 13; nt++)
#pragma unroll
        for (int c = 0; c < 4; c++) { accA[nt][c] = 0.f; accB[nt][c] = 0.f; }

    const uint32_t sA = sbase;
    const uint32_t sB = sbase + K1_A_BYTES;

    for (int kt = 0; kt < 13; kt++) {
        uint32_t a[4];
        ldsm_x4(a, sA + (uint32_t)((m0 + (lane & 15)) * 432 + kt * 32
                                   + (lane >> 4) * 16));
#pragma unroll
        for (int ntp = 0; ntp < 6; ntp++) {
            uint32_t b[4];
            int tile = 2 * ntp + (lane >> 4);
            ldsm_x4(b, sB + (uint32_t)((tile * 8 + (lane & 7)) * 432 + kt * 32
                                       + ((lane >> 3) & 1) * 16));
            mma_bf16(accA[2 * ntp],     a, b[0], b[1]);
            mma_bf16(accA[2 * ntp + 1], a, b[2], b[3]);
            ldsm_x4(b, sB + (uint32_t)(((112 + tile * 8) + (lane & 7)) * 432
                                       + kt * 32 + ((lane >> 3) & 1) * 16));
            mma_bf16(accB[2 * ntp],     a, b[0], b[1]);
            mma_bf16(accB[2 * ntp + 1], a, b[2], b[3]);
        }
        {
            uint32_t b[2];
            ldsm_x2(b, sB + (uint32_t)((96 + (lane & 7)) * 432 + kt * 32
                                       + ((lane >> 3) & 1) * 16));
            mma_bf16(accA[12], a, b[0], b[1]);
            ldsm_x2(b, sB + (uint32_t)((208 + (lane & 7)) * 432 + kt * 32
                                       + ((lane >> 3) & 1) * 16));
            mma_bf16(accB[12], a, b[0], b[1]);
        }
    }

    const int rowA = r0 + m0 + (lane >> 2);
    const int rowB = rowA + 8;
    uint32_t* d0A = &g_xp_bf[(size_t)rowA * 50];
    uint32_t* d0B = &g_xp_bf[(size_t)rowB * 50];
    uint32_t* d1A = &g_xp_bf[(size_t)MM * 50 + (size_t)rowA * 50];
    uint32_t* d1B = &g_xp_bf[(size_t)MM * 50 + (size_t)rowB * 50];
#pragma unroll
    for (int nt = 0; nt < 13; nt++) {
        int col = nt * 8 + (lane & 3) * 2;
        if (col < HH) {
            float b00 = bias_sh[col], b01 = bias_sh[col + 1];
            float b10 = bias_sh[104 + col], b11 = bias_sh[104 + col + 1];
            d0A[col >> 1] = bf16x2(accA[nt][0] + b00, accA[nt][1] + b01);
            d0B[col >> 1] = bf16x2(accA[nt][2] + b00, accA[nt][3] + b01);
            d1A[col >> 1] = bf16x2(accB[nt][0] + b10, accB[nt][1] + b11);
            d1B[col >> 1] = bf16x2(accB[nt][2] + b10, accB[nt][3] + b11);
        }
    }
}

// ---------------------------------------------------------------------------
// K2 v2.1 (mma.sync recurrent scan, SHORT CHAINS):
// 4 independent accumulator chains per tile (depth<=2); chain0 seeded with
// the xp fragment. FIX vs R12: seed loads PREDICATED on col0 < HH — warp 6's
// pad lanes (col0=100,102) indexed 1 word past the xstage buffer (SMEM OOB
// trap at the last buf/it/row).
// ---------------------------------------------------------------------------
#define K2_STRIDE 240
#define K2_OFF_B 0
#define K2_OFF_A 24960
#define K2_OFF_X 32640
#define K2_SMEM  (32640 + 51200)

__global__ void __launch_bounds__(256)
rnn_scan_mma_kernel(const float* __restrict__ Whf,
                    const float* __restrict__ Whb)
{
    extern __shared__ __align__(16) char sm2[];
    const uint32_t sbase = smem_u32(sm2);
    uint32_t* xs = (uint32_t*)(sm2 + K2_OFF_X);

    const int tid  = threadIdx.x;
    const int w    = tid >> 5;
    const int lane = tid & 31;
    const int dir  = blockIdx.y;
    const int b0   = blockIdx.x * 16;
    const float* Whh = dir ? Whb : Whf;

    for (int idx = tid; idx < 104 * 60; idx += 256) {
        int j = idx / 60, kp = idx - j * 60, k = kp * 2;
        float w0 = 0.f, w1 = 0.f;
        if (j < HH && k < HH) { w0 = Whh[j * HH + k]; w1 = Whh[j * HH + k + 1]; }
        *(uint32_t*)(sm2 + K2_OFF_B + j * K2_STRIDE + kp * 4) = bf16x2(w0, w1);
    }
    for (int idx = tid; idx < 1920; idx += 256)
        ((uint32_t*)(sm2 + K2_OFF_A))[idx] = 0u;

    const uint32_t* xpg = g_xp_bf + (size_t)dir * SS * BB * 50;
    const int base = dir ? (SS - 1) : 0;
    const int sgn  = dir ? -1 : 1;
    for (int q = 0; q < 8; q++) {
        const uint32_t* src = xpg + (size_t)(base + sgn * q) * (BB * 50) + b0 * 50;
        for (int idx = tid; idx < 800; idx += 256)
            xs[q * 800 + idx] = src[idx];
    }
    __syncthreads();

    uint32_t Bf[7][4];
    if (w < 6) {
#pragma unroll
        for (int kt = 0; kt < 7; kt++)
            ldsm_x4(Bf[kt], sbase + K2_OFF_B
                    + (uint32_t)(((2 * w + (lane >> 4)) * 8 + (lane & 7)) * K2_STRIDE
                                 + kt * 32 + ((lane >> 3) & 1) * 16));
    } else if (w == 6) {
#pragma unroll
        for (int kt = 0; kt < 7; kt++)
            ldsm_x2(Bf[kt], sbase + K2_OFF_B
                    + (uint32_t)((96 + (lane & 7)) * K2_STRIDE
                                 + kt * 32 + ((lane >> 3) & 1) * 16));
    }

    const int rowA = lane >> 2;
    const int rowB = rowA + 8;

    for (int t0 = 0; t0 < SS; t0 += 8) {
        const int buf = (t0 >> 3) & 1;

        if (t0 + 8 < SS && tid < 200) {
#pragma unroll
            for (int q = 0; q < 8; q++) {
                const char* src = (const char*)(xpg
                    + (size_t)(base + sgn * (t0 + 8 + q)) * (BB * 50) + b0 * 50);
                cp_async16(sbase + K2_OFF_X + (buf ^ 1) * 25600 + q * 3200
                           + tid * 16, src + tid * 16);
            }
        }
        asm volatile("cp.async.commit_group;" ::: "memory");

        for (int it = 0; it < 8; it++) {
            const int t = t0 + it;
            const int cur = t & 1, nxt = cur ^ 1;

            if (w < 7) {
                uint32_t a[7][4];
#pragma unroll
                for (int kt = 0; kt < 7; kt++)
                    ldsm_x4(a[kt], sbase + K2_OFF_A
                            + (uint32_t)(cur * 3840 + (lane & 15) * K2_STRIDE
                                         + kt * 32 + (lane >> 4) * 16));

                const int s = base + sgn * t;
                const uint32_t* xrow = &xs[buf * 6400 + it * 800];
                const size_t gb = ((size_t)dir * SS + s) * (BB * 50);

                const int nt0  = (w < 6) ? 2 * w : 12;
                const int col0 = nt0 * 8 + (lane & 3) * 2;
                const int col1 = col0 + 8;          // only used when w<6
                const bool c0ok = (col0 < HH);

                // ---- tile 0: 4 independent chains; chain0 seeded with xp
                //      (seed loads predicated: pad lanes would index OOB) ----
                uint32_t pA = c0ok ? xrow[rowA * 50 + (col0 >> 1)] : 0u;
                uint32_t pB = c0ok ? xrow[rowB * 50 + (col0 >> 1)] : 0u;
                float c0[4] = { bflo(pA), bfhi(pA), bflo(pB), bfhi(pB) };
                float c1[4] = {0,0,0,0}, c2[4] = {0,0,0,0}, c3[4] = {0,0,0,0};
                mma_bf16(c0, a[0], Bf[0][0], Bf[0][1]);
                mma_bf16(c1, a[2], Bf[2][0], Bf[2][1]);
                mma_bf16(c2, a[4], Bf[4][0], Bf[4][1]);
                mma_bf16(c3, a[6], Bf[6][0], Bf[6][1]);
                mma_bf16(c0, a[1], Bf[1][0], Bf[1][1]);
                mma_bf16(c1, a[3], Bf[3][0], Bf[3][1]);
                mma_bf16(c2, a[5], Bf[5][0], Bf[5][1]);

                {
                    float z0 = (c0[0] + c1[0]) + (c2[0] + c3[0]);
                    float z1 = (c0[1] + c1[1]) + (c2[1] + c3[1]);
                    float z2 = (c0[2] + c1[2]) + (c2[2] + c3[2]);
                    float z3 = (c0[3] + c1[3]) + (c2[3] + c3[3]);
                    float h0, h1, h2, h3;
                    asm("tanh.approx.f32 %0, %1;" : "=f"(h0) : "f"(z0));
                    asm("tanh.approx.f32 %0, %1;" : "=f"(h1) : "f"(z1));
                    asm("tanh.approx.f32 %0, %1;" : "=f"(h2) : "f"(z2));
                    asm("tanh.approx.f32 %0, %1;" : "=f"(h3) : "f"(z3));
                    uint32_t hA = bfpack2(h0, h1), hB = bfpack2(h2, h3);
                    if (c0ok) {
                        *(uint32_t*)(sm2 + K2_OFF_A + nxt * 3840
                                     + rowA * K2_STRIDE + col0 * 2) = hA;
                        *(uint32_t*)(sm2 + K2_OFF_A + nxt * 3840
                                     + rowB * K2_STRIDE + col0 * 2) = hB;
                        g_h_pk[gb + (b0 + rowA) * 50 + (col0 >> 1)] = hA;
                        g_h_pk[gb + (b0 + rowB) * 50 + (col0 >> 1)] = hB;
                    }
                }

                // ---- tile 1 (warps 0-5; cols always < 100) ----
                if (w < 6) {
                    uint32_t qA = xrow[rowA * 50 + (col1 >> 1)];
                    uint32_t qB = xrow[rowB * 50 + (col1 >> 1)];
                    float d0[4] = { bflo(qA), bfhi(qA), bflo(qB), bfhi(qB) };
                    float d1[4] = {0,0,0,0}, d2[4] = {0,0,0,0}, d3[4] = {0,0,0,0};
                    mma_bf16(d0, a[0], Bf[0][2], Bf[0][3]);
                    mma_bf16(d1, a[2], Bf[2][2], Bf[2][3]);
                    mma_bf16(d2, a[4], Bf[4][2], Bf[4][3]);
                    mma_bf16(d3, a[6], Bf[6][2], Bf[6][3]);
                    mma_bf16(d0, a[1], Bf[1][2], Bf[1][3]);
                    mma_bf16(d1, a[3], Bf[3][2], Bf[3][3]);
                    mma_bf16(d2, a[5], Bf[5][2], Bf[5][3]);

                    float z0 = (d0[0] + d1[0]) + (d2[0] + d3[0]);
                    float z1 = (d0[1] + d1[1]) + (d2[1] + d3[1]);
                    float z2 = (d0[2] + d1[2]) + (d2[2] + d3[2]);
                    float z3 = (d0[3] + d1[3]) + (d2[3] + d3[3]);
                    float h0, h1, h2, h3;
                    asm("tanh.approx.f32 %0, %1;" : "=f"(h0) : "f"(z0));
                    asm("tanh.approx.f32 %0, %1;" : "=f"(h1) : "f"(z1));
                    asm("tanh.approx.f32 %0, %1;" : "=f"(h2) : "f"(z2));
                    asm("tanh.approx.f32 %0, %1;" : "=f"(h3) : "f"(z3));
                    uint32_t hA = bfpack2(h0, h1), hB = bfpack2(h2, h3);
                    *(uint32_t*)(sm2 + K2_OFF_A + nxt * 3840
                                 + rowA * K2_STRIDE + col1 * 2) = hA;
                    *(uint32_t*)(sm2 + K2_OFF_A + nxt * 3840
                                 + rowB * K2_STRIDE + col1 * 2) = hB;
                    g_h_pk[gb + (b0 + rowA) * 50 + (col1 >> 1)] = hA;
                    g_h_pk[gb + (b0 + rowB) * 50 + (col1 >> 1)] = hB;
                }
            }
            if (it == 7)
                asm volatile("cp.async.wait_group 0;" ::: "memory");
            __syncthreads();
        }
    }
}

// ---------------------------------------------------------------------------
// K3 (mma.sync logits + in-fragment softmax) — unchanged (passing).
// ---------------------------------------------------------------------------
#define K3_H_BYTES (128 * 432)
#define K3_W_OFF   K3_H_BYTES
#define K3_BIAS_OFF (K3_H_BYTES + 24 * 432)
#define K3_SMEM    (K3_BIAS_OFF + 128)

__global__ void __launch_bounds__(256)
logits_mma_kernel(const float* __restrict__ btag)
{
    extern __shared__ __align__(16) char sm3[];
    const uint32_t sbase = smem_u32(sm3);
    float* bias_sh = (float*)(sm3 + K3_BIAS_OFF);

    const int tid  = threadIdx.x;
    const int wid  = tid >> 5;
    const int lane = tid & 31;
    const int row0 = blockIdx.x * 128;

    if (tid < TT) bias_sh[tid] = btag[tid];

    {
        const char* src = (const char*)g_wtag_img;
        for (int idx = tid; idx < 648; idx += 256)
            cp_async16(sbase + K3_W_OFF + idx * 16, src + idx * 16);
    }
    const uint32_t* hf = g_h_pk;
    const uint32_t* hb = g_h_pk + (size_t)MM * 50;
    for (int idx = tid; idx < 128 * 25; idx += 256) {
        int r = idx / 25, c = idx - r * 25;
        cp_async8(sbase + r * 432 + c * 8,       hf + (size_t)(row0 + r) * 50 + c * 2);
        cp_async8(sbase + r * 432 + 200 + c * 8, hb + (size_t)(row0 + r) * 50 + c * 2);
    }
    for (int idx = tid; idx < 128 * 8; idx += 256) {
        int r = idx >> 3, c = idx & 7;
        *(uint32_t*)(sm3 + r * 432 + 400 + c * 4) = 0u;
    }
    asm volatile("cp.async.commit_group;" ::: "memory");
    asm volatile("cp.async.wait_group 0;" ::: "memory");
    __syncthreads();

    const int m0 = wid * 16;
    float acc[3][4];
#pragma unroll
    for (int nt = 0; nt < 3; nt++)
#pragma unroll
        for (int c = 0; c < 4; c++) acc[nt][c] = 0.f;

    for (int kt = 0; kt < 13; kt++) {
        uint32_t a[4];
        ldsm_x4(a, sbase + (uint32_t)((m0 + (lane & 15)) * 432 + kt * 32
                                      + (lane >> 4) * 16));
        uint32_t b[4];
        ldsm_x4(b, sbase + K3_W_OFF
                + (uint32_t)(((lane >> 4) * 8 + (lane & 7)) * 432 + kt * 32
                             + ((lane >> 3) & 1) * 16));
        mma_bf16(acc[0], a, b[0], b[1]);
        mma_bf16(acc[1], a, b[2], b[3]);
        uint32_t b2[2];
        ldsm_x2(b2, sbase + K3_W_OFF
                + (uint32_t)((16 + (lane & 7)) * 432 + kt * 32
                             + ((lane >> 3) & 1) * 16));
        mma_bf16(acc[2], a, b2[0], b2[1]);
    }

    const unsigned FULL = 0xffffffffu;
    const int c0 = (lane & 3) * 2;
    float lgA[6], lgB[6];
#pragma unroll
    for (int nt = 0; nt < 3; nt++) {
        int col = nt * 8 + c0;
        lgA[2 * nt]     = (col < TT)     ? acc[nt][0] + bias_sh[col]     : -1e30f;
        lgA[2 * nt + 1] = (col + 1 < TT) ? acc[nt][1] + bias_sh[col + 1] : -1e30f;
        lgB[2 * nt]     = (col < TT)     ? acc[nt][2] + bias_sh[col]     : -1e30f;
        lgB[2 * nt + 1] = (col + 1 < TT) ? acc[nt][3] + bias_sh[col + 1] : -1e30f;
    }
    float mA = lgA[0], mB = lgB[0];
#pragma unroll
    for (int i = 1; i < 6; i++) { mA = fmaxf(mA, lgA[i]); mB = fmaxf(mB, lgB[i]); }
    mA = fmaxf(mA, __shfl_xor_sync(FULL, mA, 1));
    mA = fmaxf(mA, __shfl_xor_sync(FULL, mA, 2));
    mB = fmaxf(mB, __shfl_xor_sync(FULL, mB, 1));
    mB = fmaxf(mB, __shfl_xor_sync(FULL, mB, 2));
    float sA = 0.f, sB = 0.f;
#pragma unroll
    for (int i = 0; i < 6; i++) {
        lgA[i] = __expf(lgA[i] - mA); sA += lgA[i];
        lgB[i] = __expf(lgB[i] - mB); sB += lgB[i];
    }
    sA += __shfl_xor_sync(FULL, sA, 1);
    sA += __shfl_xor_sync(FULL, sA, 2);
    sB += __shfl_xor_sync(FULL, sB, 1);
    sB += __shfl_xor_sync(FULL, sB, 2);
    float iA = 1.0f / sA, iB = 1.0f / sB;

    const size_t rA = (size_t)(row0 + m0 + (lane >> 2)) * TT;
    const size_t rB = rA + 8 * TT;
#pragma unroll
    for (int nt = 0; nt < 3; nt++) {
        int col = nt * 8 + c0;
        if (col < TT)     { g_probs[rA + col]     = lgA[2 * nt] * iA;
                            g_probs[rB + col]     = lgB[2 * nt] * iB; }
        if (col + 1 < TT) { g_probs[rA + col + 1] = lgA[2 * nt + 1] * iA;
                            g_probs[rB + col + 1] = lgB[2 * nt + 1] * iB; }
    }
}

// ---------------------------------------------------------------------------
// K4: CRF llh (unchanged)
// ---------------------------------------------------------------------------
__global__ void __launch_bounds__(32)
crf_kernel(const int* __restrict__ y,
           const float* __restrict__ start_tr,
           const float* __restrict__ end_tr,
           const float* __restrict__ trans)
{
    __shared__ float trans_sh[TT * TT];
    __shared__ float e_em[BB][20];

    const int k = threadIdx.x;
    const int n = blockIdx.x;
    const bool lk = (k < TT);
    const unsigned FULL = 0xffffffffu;

    for (int idx = k; idx < TT * TT; idx += 32) trans_sh[idx] = trans[idx];

    const float* em_base = g_probs + (size_t)n * BB * TT;
    const int*   yrow    = y + (size_t)n * BB;

    for (int idx = k; idx < BB * TT; idx += 32) {
        int l = idx / TT, t = idx - l * TT;
        e_em[l][t] = __expf(em_base[idx]);
    }
    __syncwarp();

    float E[TT];
#pragma unroll
    for (int jj = 0; jj < TT; jj++)
        E[jj] = lk ? __expf(trans_sh[jj * TT + k]) : 0.f;

    float npart = 0.f;
    for (int l = k; l < BB; l += 32) {
        int yl = yrow[l];
        npart += em_base[l * TT + yl];
        if (l + 1 < BB) npart += trans_sh[yl * TT + yrow[l + 1]];
    }
    if (k == 0) npart += start_tr[yrow[0]] + end_tr[yrow[BB - 1]];
#pragma unroll
    for (int off = 16; off; off >>= 1)
        npart += __shfl_xor_sync(FULL, npart, off);
    const float num = npart;

    float p    = lk ? __expf(start_tr[k] + em_base[k]) : 0.f;
    float logC = 0.f;

    for (int l = 1; l < BB; l++) {
        float s0 = 0.f, s1 = 0.f, s2 = 0.f, s3 = 0.f;
#pragma unroll
        for (int jj = 0; jj < 5; jj++) {
            float pj = __shfl_sync(FULL, p, jj);
            s0 = fmaf(pj, E[jj], s0);
        }
#pragma unroll
        for (int jj = 5; jj < 10; jj++) {
            float pj = __shfl_sync(FULL, p, jj);
            s1 = fmaf(pj, E[jj], s1);
        }
#pragma unroll
        for (int jj = 10; jj < 15; jj++) {
            float pj = __shfl_sync(FULL, p, jj);
            s2 = fmaf(pj, E[jj], s2);
        }
#pragma unroll
        for (int jj = 15; jj < 19; jj++) {
            float pj = __shfl_sync(FULL, p, jj);
            s3 = fmaf(pj, E[jj], s3);
        }
        float d = (s0 + s1) + (s2 + s3);
        float z = lk ? e_em[l][k] * d : 0.f;

        if ((l & 3) == 0) {
            float mz = __shfl_sync(FULL, z, 0);
            float r;
            asm("rcp.approx.f32 %0, %1;" : "=f"(r) : "f"(mz));
            p = z * r;
            logC += __logf(mz);
        } else {
            p = z;
        }
    }

    float term = lk ? p * __expf(end_tr[k]) : 0.f;
#pragma unroll
    for (int off = 16; off; off >>= 1)
        term += __shfl_xor_sync(FULL, term, off);
    float den = logC + __logf(term);

    if (k == 0) g_res[n] = num - den;
}

// ---------------------------------------------------------------------------
// K5: deterministic final reduce
// ---------------------------------------------------------------------------
__global__ void reduce_kernel(float* __restrict__ out)
{
    __shared__ float buf[512];
    int tid = threadIdx.x;
    buf[tid] = g_res[tid];
    __syncthreads();
    for (int s = 256; s > 0; s >>= 1) {
        if (tid < s) buf[tid] += buf[tid + s];
        __syncthreads();
    }
    if (tid == 0) out[0] = buf[0];
}

// ---------------------------------------------------------------------------
extern "C" void kernel_launch(void* const* d_in, const int* in_sizes, int n_in,
                              void* d_out, int out_size)
{
    const float* x        = (const float*)d_in[0];
    const int*   y        = (const int*)d_in[1];
    const float* W_ih_f   = (const float*)d_in[2];
    const float* W_hh_f   = (const float*)d_in[3];
    const float* b_ih_f   = (const float*)d_in[4];
    const float* b_hh_f   = (const float*)d_in[5];
    const float* W_ih_b   = (const float*)d_in[6];
    const float* W_hh_b   = (const float*)d_in[7];
    const float* b_ih_b   = (const float*)d_in[8];
    const float* b_hh_b   = (const float*)d_in[9];
    const float* W_tag    = (const float*)d_in[10];
    const float* b_tag    = (const float*)d_in[11];
    const float* start_tr = (const float*)d_in[12];
    const float* end_tr   = (const float*)d_in[13];
    const float* trans    = (const float*)d_in[14];
    float*       out      = (float*)d_out;

    cudaFuncSetAttribute(proj_mma_kernel,
                         cudaFuncAttributeMaxDynamicSharedMemorySize, K1_SMEM);
    cudaFuncSetAttribute(rnn_scan_mma_kernel,
                         cudaFuncAttributeMaxDynamicSharedMemorySize, K2_SMEM);
    cudaFuncSetAttribute(logits_mma_kernel,
                         cudaFuncAttributeMaxDynamicSharedMemorySize, K3_SMEM);

    prep_kernel<<<105, 256>>>(W_ih_f, W_ih_b, W_tag);

    proj_mma_kernel<<<MM / 128, 256, K1_SMEM>>>(
        x, b_ih_f, b_hh_f, b_ih_b, b_hh_b);

    rnn_scan_mma_kernel<<<dim3(BB / 16, 2), 256, K2_SMEM>>>(W_hh_f, W_hh_b);

    logits_mma_kernel<<<MM / 128, 256, K3_SMEM>>>(b_tag);

    crf_kernel<<<SS, 32>>>(y, start_tr, end_tr, trans);

    reduce_kernel<<<1, 512>>>(out);
}

// round 14
// speedup vs baseline: 1.1064x; 1.1064x over previous
#include <cuda_runtime.h>
#include <cuda_bf16.h>
#include <cstdint>

// Problem constants
#define SS   512
#define BB   256
#define DIN  202
#define HH   100
#define TT   19
#define MM   (SS*BB)   // 131072

// ---------------- scratch (device globals; no allocations allowed) ----------
__device__ uint32_t g_xp_bf[2ll * SS * BB * 50];   // bf16x2-packed xp
__device__ uint32_t g_h_pk[2ll * SS * BB * 50];    // bf16x2-packed hidden
__device__ float g_probs[(long long)SS * BB * TT]; // softmax emissions
__device__ float g_res[SS];                        // per-sequence CRF llh
__device__ __align__(16) uint32_t g_wih_img[224 * 108];  // bf16 W_ih image (K1 B)
__device__ __align__(16) uint32_t g_wtag_img[24 * 108];  // bf16 W_tag image (K3 B)

// ---------------- helpers ----------
typedef unsigned long long u64;

__device__ __forceinline__ uint32_t smem_u32(const void* p) {
    uint32_t a;
    asm("{ .reg .u64 t; cvta.to.shared.u64 t, %1; cvt.u32.u64 %0, t; }"
        : "=r"(a) : "l"(p));
    return a;
}
__device__ __forceinline__ uint32_t bf16x2(float lo, float hi) {
    uint32_t l = (uint32_t)__bfloat16_as_ushort(__float2bfloat16_rn(lo));
    uint32_t h = (uint32_t)__bfloat16_as_ushort(__float2bfloat16_rn(hi));
    return l | (h << 16);
}
__device__ __forceinline__ uint32_t bfpack2(float lo, float hi) {
    uint32_t r;
    asm("cvt.rn.bf16x2.f32 %0, %1, %2;" : "=r"(r) : "f"(hi), "f"(lo));
    return r;
}
__device__ __forceinline__ float bflo(uint32_t u) {
    return __uint_as_float(u << 16);
}
__device__ __forceinline__ float bfhi(uint32_t u) {
    return __uint_as_float(u & 0xffff0000u);
}

__device__ __forceinline__ void ldsm_x4(uint32_t a[4], uint32_t addr) {
    asm volatile("ldmatrix.sync.aligned.m8n8.x4.shared.b16 {%0,%1,%2,%3}, [%4];"
                 : "=r"(a[0]), "=r"(a[1]), "=r"(a[2]), "=r"(a[3]) : "r"(addr));
}
__device__ __forceinline__ void ldsm_x2(uint32_t a[2], uint32_t addr) {
    asm volatile("ldmatrix.sync.aligned.m8n8.x2.shared.b16 {%0,%1}, [%2];"
                 : "=r"(a[0]), "=r"(a[1]) : "r"(addr));
}
__device__ __forceinline__ void mma_bf16(float c[4], const uint32_t a[4],
                                         uint32_t b0, uint32_t b1) {
    asm volatile("mma.sync.aligned.m16n8k16.row.col.f32.bf16.bf16.f32 "
                 "{%0,%1,%2,%3}, {%4,%5,%6,%7}, {%8,%9}, {%0,%1,%2,%3};"
                 : "+f"(c[0]), "+f"(c[1]), "+f"(c[2]), "+f"(c[3])
                 : "r"(a[0]), "r"(a[1]), "r"(a[2]), "r"(a[3]),
                   "r"(b0), "r"(b1));
}
__device__ __forceinline__ void cp_async16(uint32_t dst, const void* src) {
    asm volatile("cp.async.cg.shared.global [%0], [%1], 16;"
                 :: "r"(dst), "l"(src) : "memory");
}
__device__ __forceinline__ void cp_async8(uint32_t dst, const void* src) {
    asm volatile("cp.async.ca.shared.global [%0], [%1], 8;"
                 :: "r"(dst), "l"(src) : "memory");
}

// ---------------------------------------------------------------------------
// K0 (prep): convert W_ih (both dirs) + W_tag to bf16 SMEM-image layouts.
// ---------------------------------------------------------------------------
__global__ void prep_kernel(const float* __restrict__ Wf,
                            const float* __restrict__ Wb,
                            const float* __restrict__ Wtag)
{
    int i = blockIdx.x * 256 + threadIdx.x;
    if (i < 224 * 108) {
        int j = i / 108, kp = i - j * 108, k = 2 * kp;
        int d = j >= 112, jj = j - d * 112;
        const float* W = d ? Wb : Wf;
        float w0 = 0.f, w1 = 0.f;
        if (jj < HH) {
            if (k < DIN)     w0 = W[jj * DIN + k];
            if (k + 1 < DIN) w1 = W[jj * DIN + k + 1];
        }
        g_wih_img[i] = bf16x2(w0, w1);
    } else if (i < 224 * 108 + 24 * 108) {
        int i2 = i - 224 * 108;
        int t = i2 / 108, kp = i2 - t * 108, k = 2 * kp;
        float w0 = 0.f, w1 = 0.f;
        if (t < TT) {
            if (k < 200)     w0 = Wtag[t * 200 + k];
            if (k + 1 < 200) w1 = Wtag[t * 200 + k + 1];
        }
        g_wtag_img[i2] = bf16x2(w0, w1);
    }
}

// ---------------------------------------------------------------------------
// K1 (mma.sync bf16, BOTH dirs fused) — unchanged (passing).
// ---------------------------------------------------------------------------
#define K1_STRIDE 216
#define K1_A_BYTES (128 * K1_STRIDE * 2)
#define K1_B_BYTES (224 * K1_STRIDE * 2)
#define K1_BIAS_OFF (K1_A_BYTES + K1_B_BYTES)
#define K1_SMEM (K1_BIAS_OFF + 208 * 4)

__global__ void proj_mma_kernel(const float* __restrict__ x,
                                const float* __restrict__ bihf,
                                const float* __restrict__ bhhf,
                                const float* __restrict__ bihb,
                                const float* __restrict__ bhhb)
{
    extern __shared__ __align__(16) char smem[];
    const uint32_t sbase = smem_u32(smem);
    float* bias_sh = (float*)(smem + K1_BIAS_OFF);

    const int tid = threadIdx.x;
    const int wid = tid >> 5;
    const int lane = tid & 31;
    const int r0  = blockIdx.x * 128;

    {
        const uint32_t sB = sbase + K1_A_BYTES;
        const char* src = (const char*)g_wih_img;
        for (int idx = tid; idx < 6048; idx += 256)
            cp_async16(sB + idx * 16, src + idx * 16);
    }

    if (tid < 208) {
        int d = tid >= 104, jj = tid - d * 104;
        const float* bi = d ? bihb : bihf;
        const float* bh = d ? bhhb : bhhf;
        bias_sh[tid] = (jj < HH) ? (bi[jj] + bh[jj]) : 0.f;
    }

    for (int idx = tid; idx < 128 * 104; idx += 256) {
        int r = idx / 104, kp = idx - r * 104, k = kp * 2;
        float2 xv = make_float2(0.f, 0.f);
        if (k < DIN) xv = *(const float2*)&x[(size_t)(r0 + r) * DIN + k];
        *(uint32_t*)(smem + r * 432 + kp * 4) = bf16x2(xv.x, xv.y);
    }
    asm volatile("cp.async.commit_group;" ::: "memory");
    asm volatile("cp.async.wait_group 0;" ::: "memory");
    __syncthreads();

    const int m0 = wid * 16;
    float accA[13][4], accB[13][4];
#pragma unroll
    for (int nt = 0; nt < 13; nt++)
#pragma unroll
        for (int c = 0; c < 4; c++) { accA[nt][c] = 0.f; accB[nt][c] = 0.f; }

    const uint32_t sA = sbase;
    const uint32_t sB = sbase + K1_A_BYTES;

    for (int kt = 0; kt < 13; kt++) {
        uint32_t a[4];
        ldsm_x4(a, sA + (uint32_t)((m0 + (lane & 15)) * 432 + kt * 32
                                   + (lane >> 4) * 16));
#pragma unroll
        for (int ntp = 0; ntp < 6; ntp++) {
            uint32_t b[4];
            int tile = 2 * ntp + (lane >> 4);
            ldsm_x4(b, sB + (uint32_t)((tile * 8 + (lane & 7)) * 432 + kt * 32
                                       + ((lane >> 3) & 1) * 16));
            mma_bf16(accA[2 * ntp],     a, b[0], b[1]);
            mma_bf16(accA[2 * ntp + 1], a, b[2], b[3]);
            ldsm_x4(b, sB + (uint32_t)(((112 + tile * 8) + (lane & 7)) * 432
                                       + kt * 32 + ((lane >> 3) & 1) * 16));
            mma_bf16(accB[2 * ntp],     a, b[0], b[1]);
            mma_bf16(accB[2 * ntp + 1], a, b[2], b[3]);
        }
        {
            uint32_t b[2];
            ldsm_x2(b, sB + (uint32_t)((96 + (lane & 7)) * 432 + kt * 32
                                       + ((lane >> 3) & 1) * 16));
            mma_bf16(accA[12], a, b[0], b[1]);
            ldsm_x2(b, sB + (uint32_t)((208 + (lane & 7)) * 432 + kt * 32
                                       + ((lane >> 3) & 1) * 16));
            mma_bf16(accB[12], a, b[0], b[1]);
        }
    }

    const int rowA = r0 + m0 + (lane >> 2);
    const int rowB = rowA + 8;
    uint32_t* d0A = &g_xp_bf[(size_t)rowA * 50];
    uint32_t* d0B = &g_xp_bf[(size_t)rowB * 50];
    uint32_t* d1A = &g_xp_bf[(size_t)MM * 50 + (size_t)rowA * 50];
    uint32_t* d1B = &g_xp_bf[(size_t)MM * 50 + (size_t)rowB * 50];
#pragma unroll
    for (int nt = 0; nt < 13; nt++) {
        int col = nt * 8 + (lane & 3) * 2;
        if (col < HH) {
            float b00 = bias_sh[col], b01 = bias_sh[col + 1];
            float b10 = bias_sh[104 + col], b11 = bias_sh[104 + col + 1];
            d0A[col >> 1] = bf16x2(accA[nt][0] + b00, accA[nt][1] + b01);
            d0B[col >> 1] = bf16x2(accA[nt][2] + b00, accA[nt][3] + b01);
            d1A[col >> 1] = bf16x2(accB[nt][0] + b10, accB[nt][1] + b11);
            d1B[col >> 1] = bf16x2(accB[nt][2] + b10, accB[nt][3] + b11);
        }
    }
}

// ---------------------------------------------------------------------------
// K2 (mma.sync recurrent scan) — REVERTED to the R11 version (422us config).
// Even/odd 2-chain accumulate, ldsm inside kt loop, xp added in epilogue.
// ---------------------------------------------------------------------------
#define K2_STRIDE 240
#define K2_OFF_B 0
#define K2_OFF_A 24960
#define K2_OFF_X 32640
#define K2_SMEM  (32640 + 51200)

__global__ void __launch_bounds__(256)
rnn_scan_mma_kernel(const float* __restrict__ Whf,
                    const float* __restrict__ Whb)
{
    extern __shared__ __align__(16) char sm2[];
    const uint32_t sbase = smem_u32(sm2);
    uint32_t* xs = (uint32_t*)(sm2 + K2_OFF_X);

    const int tid  = threadIdx.x;
    const int w    = tid >> 5;
    const int lane = tid & 31;
    const int dir  = blockIdx.y;
    const int b0   = blockIdx.x * 16;
    const float* Whh = dir ? Whb : Whf;

    for (int idx = tid; idx < 104 * 60; idx += 256) {
        int j = idx / 60, kp = idx - j * 60, k = kp * 2;
        float w0 = 0.f, w1 = 0.f;
        if (j < HH && k < HH) { w0 = Whh[j * HH + k]; w1 = Whh[j * HH + k + 1]; }
        *(uint32_t*)(sm2 + K2_OFF_B + j * K2_STRIDE + kp * 4) = bf16x2(w0, w1);
    }
    for (int idx = tid; idx < 1920; idx += 256)
        ((uint32_t*)(sm2 + K2_OFF_A))[idx] = 0u;

    const uint32_t* xpg = g_xp_bf + (size_t)dir * SS * BB * 50;
    const int base = dir ? (SS - 1) : 0;
    const int sgn  = dir ? -1 : 1;
    for (int q = 0; q < 8; q++) {
        const uint32_t* src = xpg + (size_t)(base + sgn * q) * (BB * 50) + b0 * 50;
        for (int idx = tid; idx < 800; idx += 256)
            xs[q * 800 + idx] = src[idx];
    }
    __syncthreads();

    uint32_t Bf[7][4];
    if (w < 6) {
#pragma unroll
        for (int kt = 0; kt < 7; kt++)
            ldsm_x4(Bf[kt], sbase + K2_OFF_B
                    + (uint32_t)(((2 * w + (lane >> 4)) * 8 + (lane & 7)) * K2_STRIDE
                                 + kt * 32 + ((lane >> 3) & 1) * 16));
    } else if (w == 6) {
#pragma unroll
        for (int kt = 0; kt < 7; kt++)
            ldsm_x2(Bf[kt], sbase + K2_OFF_B
                    + (uint32_t)((96 + (lane & 7)) * K2_STRIDE
                                 + kt * 32 + ((lane >> 3) & 1) * 16));
    }

    const int rowA = lane >> 2;
    const int rowB = rowA + 8;

    for (int t0 = 0; t0 < SS; t0 += 8) {
        const int buf = (t0 >> 3) & 1;

        if (t0 + 8 < SS && tid < 200) {
#pragma unroll
            for (int q = 0; q < 8; q++) {
                const char* src = (const char*)(xpg
                    + (size_t)(base + sgn * (t0 + 8 + q)) * (BB * 50) + b0 * 50);
                cp_async16(sbase + K2_OFF_X + (buf ^ 1) * 25600 + q * 3200
                           + tid * 16, src + tid * 16);
            }
        }
        asm volatile("cp.async.commit_group;" ::: "memory");

        for (int it = 0; it < 8; it++) {
            const int t = t0 + it;
            const int cur = t & 1, nxt = cur ^ 1;

            if (w < 7) {
                float c0e[4] = {0,0,0,0}, c0o[4] = {0,0,0,0};
                float c1e[4] = {0,0,0,0}, c1o[4] = {0,0,0,0};
#pragma unroll
                for (int kt = 0; kt < 7; kt++) {
                    uint32_t a[4];
                    ldsm_x4(a, sbase + K2_OFF_A
                            + (uint32_t)(cur * 3840 + (lane & 15) * K2_STRIDE
                                         + kt * 32 + (lane >> 4) * 16));
                    float* c0 = (kt & 1) ? c0o : c0e;
                    mma_bf16(c0, a, Bf[kt][0], Bf[kt][1]);
                    if (w < 6) {
                        float* c1 = (kt & 1) ? c1o : c1e;
                        mma_bf16(c1, a, Bf[kt][2], Bf[kt][3]);
                    }
                }
                const int s = base + sgn * t;
                const uint32_t* xrow = &xs[buf * 6400 + it * 800];
                const size_t gb = ((size_t)dir * SS + s) * (BB * 50);

                // tile nt0
                {
                    int nt = (w < 6) ? 2 * w : 12;
                    int col = nt * 8 + (lane & 3) * 2;
                    if (col < HH) {
                        uint32_t pA = xrow[rowA * 50 + (col >> 1)];
                        uint32_t pB = xrow[rowB * 50 + (col >> 1)];
                        float z0 = c0e[0] + c0o[0] + bflo(pA);
                        float z1 = c0e[1] + c0o[1] + bfhi(pA);
                        float z2 = c0e[2] + c0o[2] + bflo(pB);
                        float z3 = c0e[3] + c0o[3] + bfhi(pB);
                        float h0, h1, h2, h3;
                        asm("tanh.approx.f32 %0, %1;" : "=f"(h0) : "f"(z0));
                        asm("tanh.approx.f32 %0, %1;" : "=f"(h1) : "f"(z1));
                        asm("tanh.approx.f32 %0, %1;" : "=f"(h2) : "f"(z2));
                        asm("tanh.approx.f32 %0, %1;" : "=f"(h3) : "f"(z3));
                        uint32_t hA = bfpack2(h0, h1), hB = bfpack2(h2, h3);
                        *(uint32_t*)(sm2 + K2_OFF_A + nxt * 3840
                                     + rowA * K2_STRIDE + col * 2) = hA;
                        *(uint32_t*)(sm2 + K2_OFF_A + nxt * 3840
                                     + rowB * K2_STRIDE + col * 2) = hB;
                        g_h_pk[gb + (b0 + rowA) * 50 + (col >> 1)] = hA;
                        g_h_pk[gb + (b0 + rowB) * 50 + (col >> 1)] = hB;
                    }
                }
                // tile nt1 (warps 0-5 only); cols always < 100
                if (w < 6) {
                    int col = (2 * w + 1) * 8 + (lane & 3) * 2;
                    uint32_t pA = xrow[rowA * 50 + (col >> 1)];
                    uint32_t pB = xrow[rowB * 50 + (col >> 1)];
                    float z0 = c1e[0] + c1o[0] + bflo(pA);
                    float z1 = c1e[1] + c1o[1] + bfhi(pA);
                    float z2 = c1e[2] + c1o[2] + bflo(pB);
                    float z3 = c1e[3] + c1o[3] + bfhi(pB);
                    float h0, h1, h2, h3;
                    asm("tanh.approx.f32 %0, %1;" : "=f"(h0) : "f"(z0));
                    asm("tanh.approx.f32 %0, %1;" : "=f"(h1) : "f"(z1));
                    asm("tanh.approx.f32 %0, %1;" : "=f"(h2) : "f"(z2));
                    asm("tanh.approx.f32 %0, %1;" : "=f"(h3) : "f"(z3));
                    uint32_t hA = bfpack2(h0, h1), hB = bfpack2(h2, h3);
                    *(uint32_t*)(sm2 + K2_OFF_A + nxt * 3840
                                 + rowA * K2_STRIDE + col * 2) = hA;
                    *(uint32_t*)(sm2 + K2_OFF_A + nxt * 3840
                                 + rowB * K2_STRIDE + col * 2) = hB;
                    g_h_pk[gb + (b0 + rowA) * 50 + (col >> 1)] = hA;
                    g_h_pk[gb + (b0 + rowB) * 50 + (col >> 1)] = hB;
                }
            }
            if (it == 7)
                asm volatile("cp.async.wait_group 0;" ::: "memory");
            __syncthreads();
        }
    }
}

// ---------------------------------------------------------------------------
// K3 (mma.sync logits + in-fragment softmax) — unchanged (passing, 20us).
// ---------------------------------------------------------------------------
#define K3_H_BYTES (128 * 432)
#define K3_W_OFF   K3_H_BYTES
#define K3_BIAS_OFF (K3_H_BYTES + 24 * 432)
#define K3_SMEM    (K3_BIAS_OFF + 128)

__global__ void __launch_bounds__(256)
logits_mma_kernel(const float* __restrict__ btag)
{
    extern __shared__ __align__(16) char sm3[];
    const uint32_t sbase = smem_u32(sm3);
    float* bias_sh = (float*)(sm3 + K3_BIAS_OFF);

    const int tid  = threadIdx.x;
    const int wid  = tid >> 5;
    const int lane = tid & 31;
    const int row0 = blockIdx.x * 128;

    if (tid < TT) bias_sh[tid] = btag[tid];

    {
        const char* src = (const char*)g_wtag_img;
        for (int idx = tid; idx < 648; idx += 256)
            cp_async16(sbase + K3_W_OFF + idx * 16, src + idx * 16);
    }
    const uint32_t* hf = g_h_pk;
    const uint32_t* hb = g_h_pk + (size_t)MM * 50;
    for (int idx = tid; idx < 128 * 25; idx += 256) {
        int r = idx / 25, c = idx - r * 25;
        cp_async8(sbase + r * 432 + c * 8,       hf + (size_t)(row0 + r) * 50 + c * 2);
        cp_async8(sbase + r * 432 + 200 + c * 8, hb + (size_t)(row0 + r) * 50 + c * 2);
    }
    for (int idx = tid; idx < 128 * 8; idx += 256) {
        int r = idx >> 3, c = idx & 7;
        *(uint32_t*)(sm3 + r * 432 + 400 + c * 4) = 0u;
    }
    asm volatile("cp.async.commit_group;" ::: "memory");
    asm volatile("cp.async.wait_group 0;" ::: "memory");
    __syncthreads();

    const int m0 = wid * 16;
    float acc[3][4];
#pragma unroll
    for (int nt = 0; nt < 3; nt++)
#pragma unroll
        for (int c = 0; c < 4; c++) acc[nt][c] = 0.f;

    for (int kt = 0; kt < 13; kt++) {
        uint32_t a[4];
        ldsm_x4(a, sbase + (uint32_t)((m0 + (lane & 15)) * 432 + kt * 32
                                      + (lane >> 4) * 16));
        uint32_t b[4];
        ldsm_x4(b, sbase + K3_W_OFF
                + (uint32_t)(((lane >> 4) * 8 + (lane & 7)) * 432 + kt * 32
                             + ((lane >> 3) & 1) * 16));
        mma_bf16(acc[0], a, b[0], b[1]);
        mma_bf16(acc[1], a, b[2], b[3]);
        uint32_t b2[2];
        ldsm_x2(b2, sbase + K3_W_OFF
                + (uint32_t)((16 + (lane & 7)) * 432 + kt * 32
                             + ((lane >> 3) & 1) * 16));
        mma_bf16(acc[2], a, b2[0], b2[1]);
    }

    const unsigned FULL = 0xffffffffu;
    const int c0 = (lane & 3) * 2;
    float lgA[6], lgB[6];
#pragma unroll
    for (int nt = 0; nt < 3; nt++) {
        int col = nt * 8 + c0;
        lgA[2 * nt]     = (col < TT)     ? acc[nt][0] + bias_sh[col]     : -1e30f;
        lgA[2 * nt + 1] = (col + 1 < TT) ? acc[nt][1] + bias_sh[col + 1] : -1e30f;
        lgB[2 * nt]     = (col < TT)     ? acc[nt][2] + bias_sh[col]     : -1e30f;
        lgB[2 * nt + 1] = (col + 1 < TT) ? acc[nt][3] + bias_sh[col + 1] : -1e30f;
    }
    float mA = lgA[0], mB = lgB[0];
#pragma unroll
    for (int i = 1; i < 6; i++) { mA = fmaxf(mA, lgA[i]); mB = fmaxf(mB, lgB[i]); }
    mA = fmaxf(mA, __shfl_xor_sync(FULL, mA, 1));
    mA = fmaxf(mA, __shfl_xor_sync(FULL, mA, 2));
    mB = fmaxf(mB, __shfl_xor_sync(FULL, mB, 1));
    mB = fmaxf(mB, __shfl_xor_sync(FULL, mB, 2));
    float sA = 0.f, sB = 0.f;
#pragma unroll
    for (int i = 0; i < 6; i++) {
        lgA[i] = __expf(lgA[i] - mA); sA += lgA[i];
        lgB[i] = __expf(lgB[i] - mB); sB += lgB[i];
    }
    sA += __shfl_xor_sync(FULL, sA, 1);
    sA += __shfl_xor_sync(FULL, sA, 2);
    sB += __shfl_xor_sync(FULL, sB, 1);
    sB += __shfl_xor_sync(FULL, sB, 2);
    float iA = 1.0f / sA, iB = 1.0f / sB;

    const size_t rA = (size_t)(row0 + m0 + (lane >> 2)) * TT;
    const size_t rB = rA + 8 * TT;
#pragma unroll
    for (int nt = 0; nt < 3; nt++) {
        int col = nt * 8 + c0;
        if (col < TT)     { g_probs[rA + col]     = lgA[2 * nt] * iA;
                            g_probs[rB + col]     = lgB[2 * nt] * iB; }
        if (col + 1 < TT) { g_probs[rA + col + 1] = lgA[2 * nt + 1] * iA;
                            g_probs[rB + col + 1] = lgB[2 * nt + 1] * iB; }
    }
}

// ---------------------------------------------------------------------------
// K4: CRF llh — rescale every 16 steps (was 4). Growth <= ~60x/step,
// 60^16 ~ 3e28 << 3.4e38 (fp32 max) -> overflow-safe; removes 3/4 of the
// shfl+rcp+log rescale events from the 255-long serial chain.
// ---------------------------------------------------------------------------
__global__ void __launch_bounds__(32)
crf_kernel(const int* __restrict__ y,
           const float* __restrict__ start_tr,
           const float* __restrict__ end_tr,
           const float* __restrict__ trans)
{
    __shared__ float trans_sh[TT * TT];
    __shared__ float e_em[BB][20];

    const int k = threadIdx.x;
    const int n = blockIdx.x;
    const bool lk = (k < TT);
    const unsigned FULL = 0xffffffffu;

    for (int idx = k; idx < TT * TT; idx += 32) trans_sh[idx] = trans[idx];

    const float* em_base = g_probs + (size_t)n * BB * TT;
    const int*   yrow    = y + (size_t)n * BB;

    for (int idx = k; idx < BB * TT; idx += 32) {
        int l = idx / TT, t = idx - l * TT;
        e_em[l][t] = __expf(em_base[idx]);
    }
    __syncwarp();

    float E[TT];
#pragma unroll
    for (int jj = 0; jj < TT; jj++)
        E[jj] = lk ? __expf(trans_sh[jj * TT + k]) : 0.f;

    float npart = 0.f;
    for (int l = k; l < BB; l += 32) {
        int yl = yrow[l];
        npart += em_base[l * TT + yl];
        if (l + 1 < BB) npart += trans_sh[yl * TT + yrow[l + 1]];
    }
    if (k == 0) npart += start_tr[yrow[0]] + end_tr[yrow[BB - 1]];
#pragma unroll
    for (int off = 16; off; off >>= 1)
        npart += __shfl_xor_sync(FULL, npart, off);
    const float num = npart;

    float p    = lk ? __expf(start_tr[k] + em_base[k]) : 0.f;
    float logC = 0.f;

    for (int l = 1; l < BB; l++) {
        float s0 = 0.f, s1 = 0.f, s2 = 0.f, s3 = 0.f;
#pragma unroll
        for (int jj = 0; jj < 5; jj++) {
            float pj = __shfl_sync(FULL, p, jj);
            s0 = fmaf(pj, E[jj], s0);
        }
#pragma unroll
        for (int jj = 5; jj < 10; jj++) {
            float pj = __shfl_sync(FULL, p, jj);
            s1 = fmaf(pj, E[jj], s1);
        }
#pragma unroll
        for (int jj = 10; jj < 15; jj++) {
            float pj = __shfl_sync(FULL, p, jj);
            s2 = fmaf(pj, E[jj], s2);
        }
#pragma unroll
        for (int jj = 15; jj < 19; jj++) {
            float pj = __shfl_sync(FULL, p, jj);
            s3 = fmaf(pj, E[jj], s3);
        }
        float d = (s0 + s1) + (s2 + s3);
        float z = lk ? e_em[l][k] * d : 0.f;

        if ((l & 15) == 0) {
            float mz = __shfl_sync(FULL, z, 0);
            float r;
            asm("rcp.approx.f32 %0, %1;" : "=f"(r) : "f"(mz));
            p = z * r;
            logC += __logf(mz);
        } else {
            p = z;
        }
    }

    float term = lk ? p * __expf(end_tr[k]) : 0.f;
#pragma unroll
    for (int off = 16; off; off >>= 1)
        term += __shfl_xor_sync(FULL, term, off);
    float den = logC + __logf(term);

    if (k == 0) g_res[n] = num - den;
}

// ---------------------------------------------------------------------------
// K5: deterministic final reduce
// ---------------------------------------------------------------------------
__global__ void reduce_kernel(float* __restrict__ out)
{
    __shared__ float buf[512];
    int tid = threadIdx.x;
    buf[tid] = g_res[tid];
    __syncthreads();
    for (int s = 256; s > 0; s >>= 1) {
        if (tid < s) buf[tid] += buf[tid + s];
        __syncthreads();
    }
    if (tid == 0) out[0] = buf[0];
}

// ---------------------------------------------------------------------------
extern "C" void kernel_launch(void* const* d_in, const int* in_sizes, int n_in,
                              void* d_out, int out_size)
{
    const float* x        = (const float*)d_in[0];
    const int*   y        = (const int*)d_in[1];
    const float* W_ih_f   = (const float*)d_in[2];
    const float* W_hh_f   = (const float*)d_in[3];
    const float* b_ih_f   = (const float*)d_in[4];
    const float* b_hh_f   = (const float*)d_in[5];
    const float* W_ih_b   = (const float*)d_in[6];
    const float* W_hh_b   = (const float*)d_in[7];
    const float* b_ih_b   = (const float*)d_in[8];
    const float* b_hh_b   = (const float*)d_in[9];
    const float* W_tag    = (const float*)d_in[10];
    const float* b_tag    = (const float*)d_in[11];
    const float* start_tr = (const float*)d_in[12];
    const float* end_tr   = (const float*)d_in[13];
    const float* trans    = (const float*)d_in[14];
    float*       out      = (float*)d_out;

    cudaFuncSetAttribute(proj_mma_kernel,
                         cudaFuncAttributeMaxDynamicSharedMemorySize, K1_SMEM);
    cudaFuncSetAttribute(rnn_scan_mma_kernel,
                         cudaFuncAttributeMaxDynamicSharedMemorySize, K2_SMEM);
    cudaFuncSetAttribute(logits_mma_kernel,
                         cudaFuncAttributeMaxDynamicSharedMemorySize, K3_SMEM);

    prep_kernel<<<105, 256>>>(W_ih_f, W_ih_b, W_tag);

    proj_mma_kernel<<<MM / 128, 256, K1_SMEM>>>(
        x, b_ih_f, b_hh_f, b_ih_b, b_hh_b);

    rnn_scan_mma_kernel<<<dim3(BB / 16, 2), 256, K2_SMEM>>>(W_hh_f, W_hh_b);

    logits_mma_kernel<<<MM / 128, 256, K3_SMEM>>>(b_tag);

    crf_kernel<<<SS, 32>>>(y, start_tr, end_tr, trans);

    reduce_kernel<<<1, 512>>>(out);
}